// round 16
// baseline (speedup 1.0000x reference)
#include <cuda_runtime.h>
#include <cuda_bf16.h>
#include <cuda_fp16.h>

// Problem constants
#define BB   512
#define SS   1024
#define SSP  (SS + 2)  // padded rows per batch (prefetch overrun; pad rows stay 0)
#define FIN  16        // features per (b,s); feature 15 is delta
#define HH   64
#define GG   192       // 3*H
#define XROWS 256      // rows per x-projection block (weights amortized 4x vs before)
#define NTP  512       // xproj threads: 8 row-groups x 64 column-triples

typedef unsigned long long u64;

// Device scratch (sanctioned alternative to cudaMalloc).
// Quad layout: per (batch,row,j): 4 halves = (z_pre, r_pre, h_pre, 0) -> one 8B access.
__device__ uint2 g_xpq[(size_t)BB * SSP * HH];   // ~268 MB

// ---- packed f32x2 helpers (bit-exact fp32, 2 FMA per fma-pipe slot) ----
__device__ __forceinline__ u64 pack2(float lo, float hi) {
    u64 r; asm("mov.b64 %0, {%1, %2};" : "=l"(r) : "f"(lo), "f"(hi)); return r;
}
__device__ __forceinline__ void unpack2(u64 v, float& lo, float& hi) {
    asm("mov.b64 {%0, %1}, %2;" : "=f"(lo), "=f"(hi) : "l"(v));
}
__device__ __forceinline__ u64 fma2(u64 a, u64 b, u64 c) {
    u64 d; asm("fma.rn.f32x2 %0, %1, %2, %3;" : "=l"(d) : "l"(a), "l"(b), "l"(c)); return d;
}
__device__ __forceinline__ u64 add2(u64 a, u64 b) {
    u64 d; asm("add.rn.f32x2 %0, %1, %2;" : "=l"(d) : "l"(a), "l"(b)); return d;
}
__device__ __forceinline__ float tanh_fast(float x) {
    float t; asm("tanh.approx.f32 %0, %1;" : "=f"(t) : "f"(x)); return t;
}

// ---------------- Kernel 1: x-projection pre-pass (quad fp16 out, biases folded) ----------------
// Thread = (row-group rg, column triple j). 256 rows/block, 512 threads: weights loaded
// once per block and amortized over 4x more rows than before. Per-row arithmetic order
// identical to the proven version (bit-identical quads). One coalesced 8B STG per row.
__global__ __launch_bounds__(NTP)
void xproj_kernel(const float* __restrict__ inputs,
                  const float* __restrict__ k_in,
                  const float* __restrict__ bias) {
    __shared__ __align__(16) float sx[XROWS * FIN];    // 16 KB
    const int tid = threadIdx.x;
    const int rg  = tid >> 6;          // row group 0..7 (32 rows each)
    const int j   = tid & 63;          // column triple
    const int bb  = blockIdx.x / (SS / XROWS);
    const int s0  = (blockIdx.x % (SS / XROWS)) * XROWS;
    const size_t row0  = (size_t)bb * SS + s0;
    const size_t drow0 = (size_t)bb * SSP + s0;

    // K weights for columns j (z), 64+j (r), 128+j (h); f32x2 pairs over f (f=15 masked)
    u64 Kz[8], Kr[8], Kh[8];
    #pragma unroll
    for (int f2 = 0; f2 < 8; f2++) {
        const int f = 2 * f2;
        const bool hv = (f + 1 < 15);
        Kz[f2] = pack2(k_in[f * GG + j],        hv ? k_in[(f + 1) * GG + j]        : 0.0f);
        Kr[f2] = pack2(k_in[f * GG + 64 + j],   hv ? k_in[(f + 1) * GG + 64 + j]   : 0.0f);
        Kh[f2] = pack2(k_in[f * GG + 128 + j],  hv ? k_in[(f + 1) * GG + 128 + j]  : 0.0f);
    }
    const float bfz = bias[j]        + bias[GG + j];
    const float bfr = bias[64 + j]   + bias[GG + 64 + j];
    const float bfh = bias[128 + j];                       // h recurrent bias stays in scan

    // stage 256 input rows (16 KB, coalesced float4)
    const float4* src = (const float4*)(inputs + row0 * FIN);
    #pragma unroll
    for (int i = 0; i < (XROWS * 4) / NTP; i++)
        ((float4*)sx)[tid + i * NTP] = src[tid + i * NTP];
    __syncthreads();

    uint2* dst = g_xpq + drow0 * HH + j;
    #pragma unroll 4
    for (int rr = 0; rr < XROWS / 8; rr++) {
        const int r = rg * (XROWS / 8) + rr;
        const ulonglong2* xr = (const ulonglong2*)(sx + r * FIN);
        u64 az0 = 0ull, az1 = 0ull, ar0 = 0ull, ar1 = 0ull, ah0 = 0ull, ah1 = 0ull;
        #pragma unroll
        for (int q = 0; q < 4; q++) {
            ulonglong2 xv = xr[q];
            az0 = fma2(xv.x, Kz[2 * q],     az0);
            ar0 = fma2(xv.x, Kr[2 * q],     ar0);
            ah0 = fma2(xv.x, Kh[2 * q],     ah0);
            az1 = fma2(xv.y, Kz[2 * q + 1], az1);
            ar1 = fma2(xv.y, Kr[2 * q + 1], ar1);
            ah1 = fma2(xv.y, Kh[2 * q + 1], ah1);
        }
        float lo, hi;
        unpack2(add2(az0, az1), lo, hi);  const float vz = bfz + (lo + hi);
        unpack2(add2(ar0, ar1), lo, hi);  const float vr = bfr + (lo + hi);
        unpack2(add2(ah0, ah1), lo, hi);  const float vh = bfh + (lo + hi);
        __half2 qa = __floats2half2_rn(vz, vr);
        __half2 qb = __floats2half2_rn(vh, 0.0f);
        uint2 quad;
        quad.x = *(const unsigned int*)&qa;
        quad.y = *(const unsigned int*)&qb;
        dst[(size_t)r * HH] = quad;     // warp: 32 consecutive j -> 256B coalesced STG.64
    }
}

// ---------------- Kernel 2: GRU scan — R14 verbatim (measured 388 us, ~99% of fma-pipe floor) ----------------
// One 64-thread CTA per batch; thread = column triple; in-thread gates via MUFU.TANH;
// one __syncthreads per step; occ 4 -> 4 desynced CTAs feeding SMSP0/1 (fma-pipe-bound).
__global__ __launch_bounds__(HH, 4)
void gru_scan_kernel(const float* __restrict__ inputs,   // (B,S,16) - for delta mean
                     const float* __restrict__ r_in,     // (64,192)
                     const float* __restrict__ bias,     // (2,192)
                     const float* __restrict__ w1,       // (64,64)
                     const float* __restrict__ b1,       // (64)
                     const float* __restrict__ bn_gamma,
                     const float* __restrict__ bn_beta,
                     const float* __restrict__ bn_mean,
                     const float* __restrict__ bn_var,
                     const float* __restrict__ w2,       // (64,1)
                     const float* __restrict__ b2,       // (1)
                     const float* __restrict__ Tp,       // (1)
                     float* __restrict__ out)            // (B,1)
{
    __shared__ __align__(16) float sm_h[2][HH];   // double-buffered hidden state
    __shared__ float sm_e[HH];
    __shared__ float sm_r[HH];

    const int j = threadIdx.x;    // column triple 0..63
    const int b = blockIdx.x;     // batch

    // Recurrent weights for columns j (z), 64+j (r), 128+j (h); f32x2 pairs over k
    u64 Rz[32], Rr[32], Rh[32];
    #pragma unroll
    for (int k2 = 0; k2 < 32; k2++) {
        Rz[k2] = pack2(r_in[(2 * k2) * GG + j],        r_in[(2 * k2 + 1) * GG + j]);
        Rr[k2] = pack2(r_in[(2 * k2) * GG + 64 + j],   r_in[(2 * k2 + 1) * GG + 64 + j]);
        Rh[k2] = pack2(r_in[(2 * k2) * GG + 128 + j],  r_in[(2 * k2 + 1) * GG + 128 + j]);
    }
    const float brh = bias[GG + 128 + j];   // only h-gate recurrent bias remains

    sm_h[0][j] = 0.0f;

    const uint2* xq = g_xpq + (size_t)b * SSP * HH + j;
    // prefetch quads for s=0,1 (kept raw; converted at use)
    uint2 q0 = xq[0];
    uint2 q1 = xq[HH];
    __syncthreads();

    for (int s = 0; s < SS; s++) {
        const int p = s & 1;

        // prefetch s+2 (padded rows: no predicate needed; pad rows are zero)
        uint2 q2 = xq[(size_t)(s + 2) * HH];

        // convert current step's quad
        const __half2 ha = *(const __half2*)&q0.x;   // (z_pre, r_pre)
        const __half2 hb = *(const __half2*)&q0.y;   // (h_pre, 0)
        const float xz0 = __low2float(ha);
        const float xr0 = __high2float(ha);
        const float xh0 = __low2float(hb);

        // three recurrent dots, all in-thread (96 fma2, 6 chains of depth 16)
        const ulonglong2* h4 = (const ulonglong2*)sm_h[p];   // broadcast LDS.128
        u64 az0 = 0ull, az1 = 0ull, ar0 = 0ull, ar1 = 0ull, ah0 = 0ull, ah1 = 0ull;
        #pragma unroll
        for (int q2i = 0; q2i < 16; q2i++) {
            ulonglong2 hv = h4[q2i];
            az0 = fma2(hv.x, Rz[2 * q2i],     az0);
            ar0 = fma2(hv.x, Rr[2 * q2i],     ar0);
            ah0 = fma2(hv.x, Rh[2 * q2i],     ah0);
            az1 = fma2(hv.y, Rz[2 * q2i + 1], az1);
            ar1 = fma2(hv.y, Rr[2 * q2i + 1], ar1);
            ah1 = fma2(hv.y, Rh[2 * q2i + 1], ah1);
        }
        float lo, hi;
        unpack2(add2(az0, az1), lo, hi);  const float az  = xz0 + (lo + hi);
        unpack2(add2(ar0, ar1), lo, hi);  const float ar_ = xr0 + (lo + hi);
        unpack2(add2(ah0, ah1), lo, hi);  const float rh_ = brh + (lo + hi);

        // gates via MUFU.TANH (sigmoid(x) = 0.5 + 0.5*tanh(x/2))
        const float z  = 0.5f + 0.5f * tanh_fast(0.5f * az);
        const float r  = 0.5f + 0.5f * tanh_fast(0.5f * ar_);
        const float hh = tanh_fast(xh0 + r * rh_);
        const float ho = sm_h[p][j];
        sm_h[p ^ 1][j] = z * (ho - hh) + hh;

        q0 = q1;
        q1 = q2;
        __syncthreads();   // the ONLY barrier per step
    }

    // final h is in buffer 0 (SS even)
    const float* hf = sm_h[0];

    // ---------- delta mean (fused; once per batch) ----------
    {
        float s = 0.0f;
        const float* dp = inputs + ((size_t)b * SS + (size_t)j * 16) * FIN + 15;
        #pragma unroll
        for (int i = 0; i < 16; i++) s += dp[(size_t)i * FIN];
        sm_r[j] = s;
    }
    __syncthreads();
    if (j < 16) sm_r[j] += sm_r[j + 16] + sm_r[j + 32] + sm_r[j + 48];
    __syncthreads();
    if (j < 4)  sm_r[j] += sm_r[j + 4] + sm_r[j + 8] + sm_r[j + 12];
    __syncthreads();
    const float db = Tp[0] * ((sm_r[0] + sm_r[1]) + (sm_r[2] + sm_r[3])) * (1.0f / (float)SS);

    // ---------- Epilogue: MLP head + BN ----------
    {
        float acc = b1[j];
        #pragma unroll 8
        for (int k = 0; k < HH; k++)
            acc += (hf[k] + db) * w1[k * HH + j];
        float hr = fmaxf(acc, 0.0f);
        float hb = (hr - bn_mean[j]) * rsqrtf(bn_var[j] + 1e-3f) * bn_gamma[j] + bn_beta[j];
        sm_e[j] = hb * w2[j];
    }
    __syncthreads();

    if (j == 0) {
        float acc = b2[0];
        #pragma unroll 8
        for (int k = 0; k < HH; k++) acc += sm_e[k];
        out[b] = acc;
    }
}

extern "C" void kernel_launch(void* const* d_in, const int* in_sizes, int n_in,
                              void* d_out, int out_size) {
    const float* inputs   = (const float*)d_in[0];
    const float* gk       = (const float*)d_in[1];
    const float* grk      = (const float*)d_in[2];
    const float* gbias    = (const float*)d_in[3];
    const float* w1       = (const float*)d_in[4];
    const float* b1       = (const float*)d_in[5];
    const float* bn_gamma = (const float*)d_in[6];
    const float* bn_beta  = (const float*)d_in[7];
    const float* bn_mean  = (const float*)d_in[8];
    const float* bn_var   = (const float*)d_in[9];
    const float* w2       = (const float*)d_in[10];
    const float* b2       = (const float*)d_in[11];
    const float* T        = (const float*)d_in[12];
    float* out = (float*)d_out;

    xproj_kernel<<<(BB * SS) / XROWS, NTP>>>(inputs, gk, gbias);
    gru_scan_kernel<<<BB, HH>>>(inputs, grk, gbias, w1, b1,
                                bn_gamma, bn_beta, bn_mean, bn_var,
                                w2, b2, T, out);
}